// round 1
// baseline (speedup 1.0000x reference)
#include <cuda_runtime.h>
#include <math.h>

#define S_LEN 20
#define U_LEN 256
#define NTOK  (S_LEN * U_LEN)      // 5120
#define VSZ   100000
#define NC    64
#define CANDN 1024
#define HD    128
#define TOPK  10
#define RHO_C 0.02f
#define VGS   24                   // padded row stride (20 vals + norm + pad)

// -------- device scratch (no allocations allowed) --------
__device__ float g_tc_ti[40];                    // b_ti1 + te[2] @ W_ti1[20:]
__device__ float g_tc_to[3 * 40];                // b_to1 + te[s] @ W_to1[20:]
__device__ float g_vg[NC * CANDN * VGS];         // candidate vec_output (+norm)  6.3MB
__device__ float g_a[NTOK * VGS];                // per-token a (+norm)

// ============ K0: fold time-embedding contributions ============
__global__ void k0_setup(const float* __restrict__ te,
                         const float* __restrict__ Wto1, const float* __restrict__ bto1,
                         const float* __restrict__ Wti1, const float* __restrict__ bti1) {
    int t = threadIdx.x;
    if (t < 40) {
        float acc = bti1[t];
        #pragma unroll
        for (int i = 0; i < 20; i++) acc += te[2 * 20 + i] * Wti1[(20 + i) * 40 + t];
        g_tc_ti[t] = acc;
    } else if (t < 160) {
        int s = (t - 40) / 40, a = (t - 40) % 40;
        float acc = bto1[a];
        #pragma unroll
        for (int i = 0; i < 20; i++) acc += te[s * 20 + i] * Wto1[(20 + i) * 40 + a];
        g_tc_to[s * 40 + a] = acc;
    }
}

// ============ K1: candidate-side MLP, directly per (centroid,cand) ============
__global__ void k1_vg(const int* __restrict__ cand, const float* __restrict__ vecs,
                      const float* __restrict__ Wti1, const float* __restrict__ Wti2,
                      const float* __restrict__ bti2) {
    __shared__ float W1s[20 * 40], W2s[40 * 20], tcs[40], b2s[20];
    int tid = threadIdx.x;
    for (int i = tid; i < 800; i += 256) { W1s[i] = Wti1[i]; W2s[i] = Wti2[i]; }
    if (tid < 40) tcs[tid] = g_tc_ti[tid];
    if (tid < 20) b2s[tid] = bti2[tid];
    __syncthreads();

    int g = blockIdx.x * 256 + tid;                 // 0..65535
    int v = cand[g];
    float in[20];
    const float4* vp = (const float4*)(vecs + (size_t)v * 20);
    #pragma unroll
    for (int q = 0; q < 5; q++) {
        float4 f = vp[q];
        in[4 * q] = f.x; in[4 * q + 1] = f.y; in[4 * q + 2] = f.z; in[4 * q + 3] = f.w;
    }
    float out[20];
    #pragma unroll
    for (int d = 0; d < 20; d++) out[d] = b2s[d];
    #pragma unroll 4
    for (int a = 0; a < 40; a++) {
        float h = tcs[a];
        #pragma unroll
        for (int i = 0; i < 20; i++) h += in[i] * W1s[i * 40 + a];
        h = fmaxf(h, 0.0f);
        #pragma unroll
        for (int d = 0; d < 20; d++) out[d] += h * W2s[a * 20 + d];
    }
    float nrm = 0.0f;
    float* dst = g_vg + (size_t)g * VGS;
    #pragma unroll
    for (int d = 0; d < 20; d++) { nrm += out[d] * out[d]; dst[d] = out[d]; }
    dst[20] = nrm;
}

// ============ K2: per-token a = 0.5*(hist + xi_out) ============
__global__ void k2_a(const int* __restrict__ x, const int* __restrict__ tslot,
                     const float* __restrict__ vecs,
                     const float* __restrict__ Wseq1, const float* __restrict__ bseq1,
                     const float* __restrict__ Wseq2, const float* __restrict__ bseq2,
                     const float* __restrict__ Wto1, const float* __restrict__ Wto2,
                     const float* __restrict__ bto2) {
    __shared__ float Ws1[100 * 40], Ws2[40 * 20], Wt1[20 * 40], Wt2[40 * 20];
    __shared__ float bs1[40], bs2[20], bt2[20], tcs[120];
    int tid = threadIdx.x;
    for (int i = tid; i < 4000; i += 128) Ws1[i] = Wseq1[i];
    for (int i = tid; i < 800; i += 128) { Ws2[i] = Wseq2[i]; Wt1[i] = Wto1[i]; Wt2[i] = Wto2[i]; }
    if (tid < 40) bs1[tid] = bseq1[tid];
    if (tid < 20) { bs2[tid] = bseq2[tid]; bt2[tid] = bto2[tid]; }
    if (tid < 120) tcs[tid] = g_tc_to[tid];
    __syncthreads();

    int n = blockIdx.x * 128 + tid;     // 5120 threads exactly
    int s = n / U_LEN, u = n % U_LEN;

    float hseq[40];
    #pragma unroll
    for (int a = 0; a < 40; a++) hseq[a] = bs1[a];

    float e[20];                        // after loop holds x_emb (k=0)
    #pragma unroll 1
    for (int p = 0; p < 5; p++) {       // concat order: shift4..shift1, x_emb
        int k = 4 - p;
        int sel = (s < k) ? s : s - k;
        int xid = x[sel * U_LEN + u];
        const float4* vp = (const float4*)(vecs + (size_t)xid * 20);
        #pragma unroll
        for (int q = 0; q < 5; q++) {
            float4 f = vp[q];
            e[4 * q] = f.x; e[4 * q + 1] = f.y; e[4 * q + 2] = f.z; e[4 * q + 3] = f.w;
        }
        #pragma unroll
        for (int i = 0; i < 20; i++) {
            float ei = e[i];
            #pragma unroll
            for (int a = 0; a < 40; a++) hseq[a] += ei * Ws1[(p * 20 + i) * 40 + a];
        }
    }

    float ho[20];
    #pragma unroll
    for (int d = 0; d < 20; d++) ho[d] = bs2[d];
    #pragma unroll 4
    for (int a = 0; a < 40; a++) {
        float r = fmaxf(hseq[a], 0.0f);
        #pragma unroll
        for (int d = 0; d < 20; d++) ho[d] += r * Ws2[a * 20 + d];
    }

    int t24 = tslot[n] % 24;
    int seg = (t24 >= 22 || t24 < 6) ? 0 : (t24 < 14 ? 1 : 2);
    float hto[40];
    #pragma unroll
    for (int a = 0; a < 40; a++) hto[a] = tcs[seg * 40 + a];
    #pragma unroll
    for (int i = 0; i < 20; i++) {
        float ei = e[i];
        #pragma unroll
        for (int a = 0; a < 40; a++) hto[a] += ei * Wt1[i * 40 + a];
    }
    float xo[20];
    #pragma unroll
    for (int d = 0; d < 20; d++) xo[d] = bt2[d];
    #pragma unroll 4
    for (int a = 0; a < 40; a++) {
        float r = fmaxf(hto[a], 0.0f);
        #pragma unroll
        for (int d = 0; d < 20; d++) xo[d] += r * Wt2[a * 20 + d];
    }

    float nrm = 0.0f;
    float* dst = g_a + (size_t)n * VGS;
    #pragma unroll
    for (int d = 0; d < 20; d++) {
        float av = 0.5f * (ho[d] + xo[d]);
        dst[d] = av; nrm += av * av;
    }
    dst[20] = nrm;
}

// ============ K3: d2 scoring + top-10 + softmax-gather, one block per token ============
__global__ void k3_score(const int* __restrict__ x, const int* __restrict__ Iarr,
                         const int* __restrict__ cand, const float* __restrict__ Eemb,
                         float* __restrict__ out) {
    __shared__ float a_s[20];
    __shared__ float a_nrm_s;
    __shared__ int   c_idx_s;
    __shared__ float wv[8];  __shared__ int wi[8];
    __shared__ float tv[TOPK]; __shared__ int tj[TOPK];
    __shared__ int   winner;
    __shared__ float sw[12];  __shared__ int si[12];
    __shared__ float inv_s;

    int tid = threadIdx.x;
    int n = blockIdx.x;
    if (tid < 20) a_s[tid] = g_a[(size_t)n * VGS + tid];
    if (tid == 20) a_nrm_s = g_a[(size_t)n * VGS + 20];
    if (tid == 21) c_idx_s = Iarr[x[n]];
    __syncthreads();

    int cbase = c_idx_s * CANDN;
    float an = a_nrm_s;
    float d2r[4];
    #pragma unroll
    for (int q = 0; q < 4; q++) {
        int j = tid + 256 * q;
        const float4* vp = (const float4*)(g_vg + (size_t)(cbase + j) * VGS);
        float4 f0 = vp[0], f1 = vp[1], f2 = vp[2], f3 = vp[3], f4 = vp[4];
        float vn = ((const float*)vp)[20];
        float dot =
            f0.x * a_s[0]  + f0.y * a_s[1]  + f0.z * a_s[2]  + f0.w * a_s[3]  +
            f1.x * a_s[4]  + f1.y * a_s[5]  + f1.z * a_s[6]  + f1.w * a_s[7]  +
            f2.x * a_s[8]  + f2.y * a_s[9]  + f2.z * a_s[10] + f2.w * a_s[11] +
            f3.x * a_s[12] + f3.y * a_s[13] + f3.z * a_s[14] + f3.w * a_s[15] +
            f4.x * a_s[16] + f4.y * a_s[17] + f4.z * a_s[18] + f4.w * a_s[19];
        float d2 = an + vn - 2.0f * dot;
        d2r[q] = fmaxf(d2, 1e-12f);   // clamp BEFORE ordering: matches ref tie structure
    }

    int lane = tid & 31, warp = tid >> 5;
    for (int k = 0; k < TOPK; k++) {
        float bv = 3.4e38f; int bj = 0x7fffffff;
        #pragma unroll
        for (int q = 0; q < 4; q++) {
            int j = tid + 256 * q;
            if (d2r[q] < bv || (d2r[q] == bv && j < bj)) { bv = d2r[q]; bj = j; }
        }
        #pragma unroll
        for (int off = 16; off > 0; off >>= 1) {
            float ov = __shfl_down_sync(0xffffffffu, bv, off);
            int   oj = __shfl_down_sync(0xffffffffu, bj, off);
            if (ov < bv || (ov == bv && oj < bj)) { bv = ov; bj = oj; }
        }
        if (lane == 0) { wv[warp] = bv; wi[warp] = bj; }
        __syncthreads();
        if (tid == 0) {
            float fv = wv[0]; int fj = wi[0];
            #pragma unroll
            for (int w = 1; w < 8; w++)
                if (wv[w] < fv || (wv[w] == fv && wi[w] < fj)) { fv = wv[w]; fj = wi[w]; }
            tv[k] = fv; tj[k] = fj; winner = fj;
        }
        __syncthreads();
        int wj = winner;
        if ((wj & 255) == tid) d2r[wj >> 8] = 3.4e38f;   // retire selected candidate
    }

    // ---- finalize: softmax over [10 scores, 1.0], weighted embedding sum ----
    if (tid < TOPK) {
        sw[tid] = expf(-RHO_C * sqrtf(tv[tid]));
        si[tid] = cand[cbase + tj[tid]];
    } else if (tid == TOPK) {
        sw[TOPK] = 1.0f;
        si[TOPK] = x[n];
    }
    __syncthreads();
    if (tid < 11) sw[tid] = expf(sw[tid] - 1.0f);   // max of vals is exactly 1.0 (self)
    __syncthreads();
    if (tid == 0) {
        float ssum = 0.0f;
        #pragma unroll
        for (int k = 0; k < 11; k++) ssum += sw[k];
        inv_s = 1.0f / ssum;
    }
    __syncthreads();
    if (tid < HD) {
        float acc = 0.0f;
        #pragma unroll
        for (int k = 0; k < 11; k++)
            acc += sw[k] * Eemb[(size_t)si[k] * HD + tid];
        out[(size_t)n * HD + tid] = acc * inv_s;
    }
}

// ============ launch ============
extern "C" void kernel_launch(void* const* d_in, const int* in_sizes, int n_in,
                              void* d_out, int out_size) {
    const int*   x     = (const int*)  d_in[0];
    const int*   tslot = (const int*)  d_in[1];
    const float* vecs  = (const float*)d_in[2];
    const float* Eemb  = (const float*)d_in[3];
    const int*   Iarr  = (const int*)  d_in[4];
    const int*   cand  = (const int*)  d_in[5];
    const float* te    = (const float*)d_in[6];
    const float* Wseq1 = (const float*)d_in[7];
    const float* bseq1 = (const float*)d_in[8];
    const float* Wseq2 = (const float*)d_in[9];
    const float* bseq2 = (const float*)d_in[10];
    const float* Wto1  = (const float*)d_in[11];
    const float* bto1  = (const float*)d_in[12];
    const float* Wto2  = (const float*)d_in[13];
    const float* bto2  = (const float*)d_in[14];
    const float* Wti1  = (const float*)d_in[15];
    const float* bti1  = (const float*)d_in[16];
    const float* Wti2  = (const float*)d_in[17];
    const float* bti2  = (const float*)d_in[18];
    float* out = (float*)d_out;

    k0_setup<<<1, 160>>>(te, Wto1, bto1, Wti1, bti1);
    k1_vg<<<NC * CANDN / 256, 256>>>(cand, vecs, Wti1, Wti2, bti2);
    k2_a<<<NTOK / 128, 128>>>(x, tslot, vecs, Wseq1, bseq1, Wseq2, bseq2, Wto1, Wto2, bto2);
    k3_score<<<NTOK, 256>>>(x, Iarr, cand, Eemb, out);
}

// round 2
// speedup vs baseline: 1.3438x; 1.3438x over previous
#include <cuda_runtime.h>
#include <math.h>

#define S_LEN 20
#define U_LEN 256
#define NTOK  5120
#define NC    64
#define CANDN 1024
#define HD    128
#define TOPK  10
#define RHO_C 0.02f
#define VGS   24          // padded row stride (20 vals + norm + pad), 96B
#define CHUNK 32
#define MAXCH 160         // worst-case chunks per centroid (5120/32)

// -------- device scratch --------
__device__ float g_tc_ti[40];
__device__ float g_tc_to[120];
__device__ float g_vg[NC * CANDN * VGS];   // 6.3MB candidate table (+norm)
__device__ float g_a[NTOK * VGS];          // per-token a (+norm)
__device__ int   g_cnt[NC];
__device__ int   g_tok[NC * NTOK];         // 1.3MB bucket lists

// ============ K0: fold time-embeddings, zero counters ============
__global__ void k0_setup(const float* __restrict__ te,
                         const float* __restrict__ Wto1, const float* __restrict__ bto1,
                         const float* __restrict__ Wti1, const float* __restrict__ bti1) {
    int t = threadIdx.x;
    if (t < 40) {
        float acc = bti1[t];
        #pragma unroll
        for (int i = 0; i < 20; i++) acc += te[2 * 20 + i] * Wti1[(20 + i) * 40 + t];
        g_tc_ti[t] = acc;
    } else if (t < 160) {
        int s = (t - 40) / 40, a = (t - 40) % 40;
        float acc = bto1[a];
        #pragma unroll
        for (int i = 0; i < 20; i++) acc += te[s * 20 + i] * Wto1[(20 + i) * 40 + a];
        g_tc_to[s * 40 + a] = acc;
    } else if (t < 160 + NC) {
        g_cnt[t - 160] = 0;
    }
}

// ============ K_mid: fused candidate MLP (blocks 0..255) + token MLP (256..275) + bucketing (276) ============
__global__ void k_mid(const int* __restrict__ x, const int* __restrict__ tslot,
                      const float* __restrict__ vecs, const int* __restrict__ cand,
                      const int* __restrict__ Iarr,
                      const float* __restrict__ Wseq1, const float* __restrict__ bseq1,
                      const float* __restrict__ Wseq2, const float* __restrict__ bseq2,
                      const float* __restrict__ Wto1, const float* __restrict__ Wto2,
                      const float* __restrict__ bto2,
                      const float* __restrict__ Wti1, const float* __restrict__ Wti2,
                      const float* __restrict__ bti2) {
    __shared__ float sb[6600];
    int b = blockIdx.x, tid = threadIdx.x;

    if (b < 256) {
        // ---- candidate-side MLP: 65536 rows ----
        float* W1s = sb;            // 800
        float* W2s = sb + 800;      // 800
        float* tcs = sb + 1600;     // 40
        float* b2s = sb + 1640;     // 20
        for (int i = tid; i < 800; i += 256) { W1s[i] = Wti1[i]; W2s[i] = Wti2[i]; }
        if (tid < 40) tcs[tid] = g_tc_ti[tid];
        if (tid < 20) b2s[tid] = bti2[tid];
        __syncthreads();

        int g = b * 256 + tid;
        int v = cand[g];
        float in[20];
        const float4* vp = (const float4*)(vecs + (size_t)v * 20);
        #pragma unroll
        for (int q = 0; q < 5; q++) {
            float4 f = vp[q];
            in[4 * q] = f.x; in[4 * q + 1] = f.y; in[4 * q + 2] = f.z; in[4 * q + 3] = f.w;
        }
        float out[20];
        #pragma unroll
        for (int d = 0; d < 20; d++) out[d] = b2s[d];
        #pragma unroll 4
        for (int a = 0; a < 40; a++) {
            float h = tcs[a];
            #pragma unroll
            for (int i = 0; i < 20; i++) h += in[i] * W1s[i * 40 + a];
            h = fmaxf(h, 0.0f);
            #pragma unroll
            for (int d = 0; d < 20; d++) out[d] += h * W2s[a * 20 + d];
        }
        float nrm = 0.0f;
        float* dst = g_vg + (size_t)g * VGS;
        #pragma unroll
        for (int d = 0; d < 20; d++) { nrm += out[d] * out[d]; dst[d] = out[d]; }
        dst[20] = nrm;

    } else if (b < 276) {
        // ---- token-side a = 0.5*(hist + xi_out): 5120 tokens ----
        float* Ws1 = sb;            // 4000
        float* Ws2 = sb + 4000;     // 800
        float* Wt1 = sb + 4800;     // 800
        float* Wt2 = sb + 5600;     // 800
        __shared__ float bs1[40], bs2[20], bt2s[20], tcs2[120];
        for (int i = tid; i < 4000; i += 256) Ws1[i] = Wseq1[i];
        for (int i = tid; i < 800; i += 256) { Ws2[i] = Wseq2[i]; Wt1[i] = Wto1[i]; Wt2[i] = Wto2[i]; }
        if (tid < 40) bs1[tid] = bseq1[tid];
        if (tid < 20) { bs2[tid] = bseq2[tid]; bt2s[tid] = bto2[tid]; }
        if (tid < 120) tcs2[tid] = g_tc_to[tid];
        __syncthreads();

        int n = (b - 256) * 256 + tid;
        int s = n / U_LEN, u = n % U_LEN;

        float hseq[40];
        #pragma unroll
        for (int a = 0; a < 40; a++) hseq[a] = bs1[a];

        float e[20];
        #pragma unroll 1
        for (int p = 0; p < 5; p++) {
            int k = 4 - p;
            int sel = (s < k) ? s : s - k;
            int xid = x[sel * U_LEN + u];
            const float4* vp = (const float4*)(vecs + (size_t)xid * 20);
            #pragma unroll
            for (int q = 0; q < 5; q++) {
                float4 f = vp[q];
                e[4 * q] = f.x; e[4 * q + 1] = f.y; e[4 * q + 2] = f.z; e[4 * q + 3] = f.w;
            }
            #pragma unroll
            for (int i = 0; i < 20; i++) {
                float ei = e[i];
                #pragma unroll
                for (int a = 0; a < 40; a++) hseq[a] += ei * Ws1[(p * 20 + i) * 40 + a];
            }
        }

        float ho[20];
        #pragma unroll
        for (int d = 0; d < 20; d++) ho[d] = bs2[d];
        #pragma unroll 4
        for (int a = 0; a < 40; a++) {
            float r = fmaxf(hseq[a], 0.0f);
            #pragma unroll
            for (int d = 0; d < 20; d++) ho[d] += r * Ws2[a * 20 + d];
        }

        int t24 = tslot[n] % 24;
        int seg = (t24 >= 22 || t24 < 6) ? 0 : (t24 < 14 ? 1 : 2);
        float hto[40];
        #pragma unroll
        for (int a = 0; a < 40; a++) hto[a] = tcs2[seg * 40 + a];
        #pragma unroll
        for (int i = 0; i < 20; i++) {
            float ei = e[i];
            #pragma unroll
            for (int a = 0; a < 40; a++) hto[a] += ei * Wt1[i * 40 + a];
        }
        float xo[20];
        #pragma unroll
        for (int d = 0; d < 20; d++) xo[d] = bt2s[d];
        #pragma unroll 4
        for (int a = 0; a < 40; a++) {
            float r = fmaxf(hto[a], 0.0f);
            #pragma unroll
            for (int d = 0; d < 20; d++) xo[d] += r * Wt2[a * 20 + d];
        }

        float nrm = 0.0f;
        float* dst = g_a + (size_t)n * VGS;
        #pragma unroll
        for (int d = 0; d < 20; d++) {
            float av = 0.5f * (ho[d] + xo[d]);
            dst[d] = av; nrm += av * av;
        }
        dst[20] = nrm;

    } else {
        // ---- bucket tokens by centroid ----
        for (int i = tid; i < NTOK; i += 256) {
            int c = Iarr[x[i]];
            int p = atomicAdd(&g_cnt[c], 1);
            g_tok[c * NTOK + p] = i;
        }
    }
}

// ============ K3: 32 tokens/block, broadcast candidate rows, per-lane top-10 ============
__global__ void __launch_bounds__(256, 2)
k3_score(const int* __restrict__ x, const int* __restrict__ cand,
         const float* __restrict__ Eemb, float* __restrict__ out) {
    int cid = blockIdx.x;          // 0..63
    int b   = blockIdx.y;          // 0..MAXCH-1
    int cnt = g_cnt[cid];
    int start = b * CHUNK;
    if (start >= cnt) return;
    int nIn = min(CHUNK, cnt - start);

    int tid = threadIdx.x, lane = tid & 31, warp = tid >> 5;

    __shared__ unsigned long long part[8][32][TOPK];  // 20KB
    __shared__ float sw_s[32][12];
    __shared__ int   si_s[32][12];
    __shared__ int   tok_s[32];

    if (tid < 32) tok_s[tid] = g_tok[cid * NTOK + start + min(tid, nIn - 1)];
    __syncthreads();

    int token = tok_s[lane];

    // a-vector in registers
    const float* ap = g_a + (size_t)token * VGS;
    float4 A0 = *(const float4*)(ap +  0);
    float4 A1 = *(const float4*)(ap +  4);
    float4 A2 = *(const float4*)(ap +  8);
    float4 A3 = *(const float4*)(ap + 12);
    float4 A4 = *(const float4*)(ap + 16);
    float  an = ap[20];

    int cbase = cid * CANDN;
    const float* vg = g_vg + (size_t)cbase * VGS;

    unsigned long long tk[TOPK];
    #pragma unroll
    for (int q = 0; q < TOPK; q++) tk[q] = 0xFFFFFFFFFFFFFFFFull;

    int j0 = warp * 128;
    #pragma unroll 2
    for (int jj = 0; jj < 128; jj++) {
        int j = j0 + jj;
        const float* vp = vg + (size_t)j * VGS;
        float4 f0 = *(const float4*)(vp +  0);
        float4 f1 = *(const float4*)(vp +  4);
        float4 f2 = *(const float4*)(vp +  8);
        float4 f3 = *(const float4*)(vp + 12);
        float4 f4 = *(const float4*)(vp + 16);
        float  vn = vp[20];
        float dot =
            f0.x * A0.x + f0.y * A0.y + f0.z * A0.z + f0.w * A0.w +
            f1.x * A1.x + f1.y * A1.y + f1.z * A1.z + f1.w * A1.w +
            f2.x * A2.x + f2.y * A2.y + f2.z * A2.z + f2.w * A2.w +
            f3.x * A3.x + f3.y * A3.y + f3.z * A3.z + f3.w * A3.w +
            f4.x * A4.x + f4.y * A4.y + f4.z * A4.z + f4.w * A4.w;
        float d2 = fmaxf(an + vn - 2.0f * dot, 1e-12f);
        unsigned long long key =
            ((unsigned long long)__float_as_uint(d2) << 32) | (unsigned)j;
        if (key < tk[TOPK - 1]) {
            unsigned long long cur = key;
            #pragma unroll
            for (int q = 0; q < TOPK; q++) {
                unsigned long long lo = cur < tk[q] ? cur : tk[q];
                unsigned long long hi = cur < tk[q] ? tk[q] : cur;
                tk[q] = lo; cur = hi;
            }
        }
    }
    #pragma unroll
    for (int q = 0; q < TOPK; q++) part[warp][lane][q] = tk[q];
    __syncthreads();

    // ---- merge 8 sorted lists per token + softmax weights ----
    if (tid < 32 && tid < nIn) {
        int t = tid;
        unsigned long long h[8];
        int p[8];
        #pragma unroll
        for (int w = 0; w < 8; w++) { h[w] = part[w][t][0]; p[w] = 1; }
        float ssum = 1.0f;   // self term exp(1-1)=1
        #pragma unroll
        for (int k = 0; k < TOPK; k++) {
            unsigned long long best = h[0]; int bw = 0;
            #pragma unroll
            for (int w = 1; w < 8; w++) if (h[w] < best) { best = h[w]; bw = w; }
            #pragma unroll
            for (int w = 0; w < 8; w++)
                if (bw == w) { h[w] = (p[w] < TOPK) ? part[w][t][p[w]] : 0xFFFFFFFFFFFFFFFFull; p[w]++; }
            float d2 = __uint_as_float((unsigned)(best >> 32));
            int   j  = (int)(best & 0xffffffffu);
            float sc = expf(-RHO_C * sqrtf(d2));
            float e  = expf(sc - 1.0f);
            ssum += e;
            sw_s[t][k] = e;
            si_s[t][k] = cand[cbase + j];
        }
        sw_s[t][TOPK] = 1.0f;
        si_s[t][TOPK] = x[tok_s[t]];
        float inv = 1.0f / ssum;
        #pragma unroll
        for (int k = 0; k < 11; k++) sw_s[t][k] *= inv;
    }
    __syncthreads();

    // ---- weighted embedding gather: (token, 16-dim group) per thread ----
    int t  = tid >> 3;
    int pg = tid & 7;
    if (t < nIn) {
        int token2 = tok_s[t];
        float4 a0 = make_float4(0.f, 0.f, 0.f, 0.f), a1 = a0, a2 = a0, a3 = a0;
        #pragma unroll
        for (int k = 0; k < 11; k++) {
            float w = sw_s[t][k];
            const float4* ep = (const float4*)(Eemb + (size_t)si_s[t][k] * HD + pg * 16);
            float4 e0 = ep[0], e1 = ep[1], e2 = ep[2], e3 = ep[3];
            a0.x += w * e0.x; a0.y += w * e0.y; a0.z += w * e0.z; a0.w += w * e0.w;
            a1.x += w * e1.x; a1.y += w * e1.y; a1.z += w * e1.z; a1.w += w * e1.w;
            a2.x += w * e2.x; a2.y += w * e2.y; a2.z += w * e2.z; a2.w += w * e2.w;
            a3.x += w * e3.x; a3.y += w * e3.y; a3.z += w * e3.z; a3.w += w * e3.w;
        }
        float4* op = (float4*)(out + (size_t)token2 * HD + pg * 16);
        op[0] = a0; op[1] = a1; op[2] = a2; op[3] = a3;
    }
}

// ============ launch ============
extern "C" void kernel_launch(void* const* d_in, const int* in_sizes, int n_in,
                              void* d_out, int out_size) {
    const int*   x     = (const int*)  d_in[0];
    const int*   tslot = (const int*)  d_in[1];
    const float* vecs  = (const float*)d_in[2];
    const float* Eemb  = (const float*)d_in[3];
    const int*   Iarr  = (const int*)  d_in[4];
    const int*   cand  = (const int*)  d_in[5];
    const float* te    = (const float*)d_in[6];
    const float* Wseq1 = (const float*)d_in[7];
    const float* bseq1 = (const float*)d_in[8];
    const float* Wseq2 = (const float*)d_in[9];
    const float* bseq2 = (const float*)d_in[10];
    const float* Wto1  = (const float*)d_in[11];
    const float* bto1  = (const float*)d_in[12];
    const float* Wto2  = (const float*)d_in[13];
    const float* bto2  = (const float*)d_in[14];
    const float* Wti1  = (const float*)d_in[15];
    const float* bti1  = (const float*)d_in[16];
    const float* Wti2  = (const float*)d_in[17];
    const float* bti2  = (const float*)d_in[18];
    float* out = (float*)d_out;

    k0_setup<<<1, 256>>>(te, Wto1, bto1, Wti1, bti1);
    k_mid<<<277, 256>>>(x, tslot, vecs, cand, Iarr,
                        Wseq1, bseq1, Wseq2, bseq2,
                        Wto1, Wto2, bto2, Wti1, Wti2, bti2);
    k3_score<<<dim3(NC, MAXCH), 256>>>(x, cand, Eemb, out);
}

// round 3
// speedup vs baseline: 1.6415x; 1.2216x over previous
#include <cuda_runtime.h>
#include <math.h>

#define S_LEN 20
#define U_LEN 256
#define NTOK  5120
#define NC    64
#define CANDN 1024
#define HD    128
#define TOPK  10
#define RHO_C 0.02f
#define VGS   24          // padded row stride (20 vals + norm + pad), 96B
#define CHUNK 32
#define NWORK_MAX 224     // sum ceil(cnt/32) <= 5120/32 + 64

// -------- device scratch --------
__device__ float g_vg[NC * CANDN * VGS];   // candidate vec_output (+norm)
__device__ float g_a[NTOK * VGS];          // per-token a (+norm)
__device__ int   g_cnt[NC];
__device__ int   g_tok[NC * NTOK];
__device__ int2  g_work[NWORK_MAX + 32];
__device__ int   g_nwork;

// ============ K_mid: candidate MLP (0..255) | token MLP x2 threads (256..295) | bucket+worklist (296) ============
__global__ void k_mid(const int* __restrict__ x, const int* __restrict__ tslot,
                      const float* __restrict__ vecs, const int* __restrict__ cand,
                      const int* __restrict__ Iarr, const float* __restrict__ te,
                      const float* __restrict__ Wseq1, const float* __restrict__ bseq1,
                      const float* __restrict__ Wseq2, const float* __restrict__ bseq2,
                      const float* __restrict__ Wto1, const float* __restrict__ bto1,
                      const float* __restrict__ Wto2, const float* __restrict__ bto2,
                      const float* __restrict__ Wti1, const float* __restrict__ bti1,
                      const float* __restrict__ Wti2, const float* __restrict__ bti2) {
    __shared__ float sb[6600];
    int b = blockIdx.x, tid = threadIdx.x;

    if (b < 256) {
        // ---- candidate-side MLP: 65536 rows ----
        float* W1s = sb;            // 800
        float* W2s = sb + 800;      // 800
        float* tcs = sb + 1600;     // 40 : b_ti1 + te[2] @ W_ti1[20:]
        float* b2s = sb + 1640;     // 20
        for (int i = tid; i < 800; i += 256) { W1s[i] = Wti1[i]; W2s[i] = Wti2[i]; }
        if (tid < 40) {
            float acc = bti1[tid];
            #pragma unroll
            for (int i = 0; i < 20; i++) acc += te[40 + i] * Wti1[(20 + i) * 40 + tid];
            tcs[tid] = acc;
        }
        if (tid >= 64 && tid < 84) b2s[tid - 64] = bti2[tid - 64];
        __syncthreads();

        int g = b * 256 + tid;
        int v = cand[g];
        float in[20];
        const float4* vp = (const float4*)(vecs + (size_t)v * 20);
        #pragma unroll
        for (int q = 0; q < 5; q++) {
            float4 f = vp[q];
            in[4 * q] = f.x; in[4 * q + 1] = f.y; in[4 * q + 2] = f.z; in[4 * q + 3] = f.w;
        }
        float out[20];
        #pragma unroll
        for (int d = 0; d < 20; d++) out[d] = b2s[d];
        #pragma unroll 4
        for (int a = 0; a < 40; a++) {
            float h = tcs[a];
            #pragma unroll
            for (int i = 0; i < 20; i++) h += in[i] * W1s[i * 40 + a];
            h = fmaxf(h, 0.0f);
            #pragma unroll
            for (int d = 0; d < 20; d++) out[d] += h * W2s[a * 20 + d];
        }
        float nrm = 0.0f;
        float* dst = g_vg + (size_t)g * VGS;
        #pragma unroll
        for (int d = 0; d < 20; d++) { nrm += out[d] * out[d]; dst[d] = out[d]; }
        dst[20] = nrm;

    } else if (b < 296) {
        // ---- token MLP, 2 threads per token (each: 20 of 40 hidden units) ----
        float* Ws1 = sb;            // 4000
        float* Ws2 = sb + 4000;     // 800
        float* Wt1 = sb + 4800;     // 800
        float* Wt2 = sb + 5600;     // 800
        __shared__ float bs1[40], bs2[20], bt2s[20], tcs2[120];
        for (int i = tid; i < 4000; i += 256) Ws1[i] = Wseq1[i];
        for (int i = tid; i < 800; i += 256) { Ws2[i] = Wseq2[i]; Wt1[i] = Wto1[i]; Wt2[i] = Wto2[i]; }
        if (tid < 40) bs1[tid] = bseq1[tid];
        if (tid >= 64 && tid < 84) { bs2[tid - 64] = bseq2[tid - 64]; bt2s[tid - 64] = bto2[tid - 64]; }
        if (tid >= 128 && tid < 248) {
            int t = tid - 128, s = t / 40, a = t % 40;
            float acc = bto1[a];
            #pragma unroll
            for (int i = 0; i < 20; i++) acc += te[s * 20 + i] * Wto1[(20 + i) * 40 + a];
            tcs2[t] = acc;
        }
        __syncthreads();

        int pid = (b - 256) * 256 + tid;
        int n = pid >> 1, h = pid & 1;
        int s = n / U_LEN, u = n % U_LEN;
        int hb = h * 20;

        float hs[20];
        #pragma unroll
        for (int a = 0; a < 20; a++) hs[a] = bs1[hb + a];

        float e[20];
        #pragma unroll 1
        for (int p = 0; p < 5; p++) {
            int k = 4 - p;
            int sel = (s < k) ? s : s - k;
            int xid = x[sel * U_LEN + u];
            const float4* vp = (const float4*)(vecs + (size_t)xid * 20);
            #pragma unroll
            for (int q = 0; q < 5; q++) {
                float4 f = vp[q];
                e[4 * q] = f.x; e[4 * q + 1] = f.y; e[4 * q + 2] = f.z; e[4 * q + 3] = f.w;
            }
            #pragma unroll
            for (int i = 0; i < 20; i++) {
                float ei = e[i];
                #pragma unroll
                for (int a = 0; a < 20; a++) hs[a] += ei * Ws1[(p * 20 + i) * 40 + hb + a];
            }
        }

        // layer2 partial for seq path (frees hs)
        float po[20];
        #pragma unroll
        for (int d = 0; d < 20; d++) po[d] = 0.0f;
        #pragma unroll 4
        for (int a = 0; a < 20; a++) {
            float r = fmaxf(hs[a], 0.0f);
            #pragma unroll
            for (int d = 0; d < 20; d++) po[d] += r * Ws2[(hb + a) * 20 + d];
        }

        int t24 = tslot[n] % 24;
        int seg = (t24 >= 22 || t24 < 6) ? 0 : (t24 < 14 ? 1 : 2);
        float ht[20];
        #pragma unroll
        for (int a = 0; a < 20; a++) ht[a] = tcs2[seg * 40 + hb + a];
        #pragma unroll
        for (int i = 0; i < 20; i++) {
            float ei = e[i];
            #pragma unroll
            for (int a = 0; a < 20; a++) ht[a] += ei * Wt1[i * 40 + hb + a];
        }
        float px[20];
        #pragma unroll
        for (int d = 0; d < 20; d++) px[d] = 0.0f;
        #pragma unroll 4
        for (int a = 0; a < 20; a++) {
            float r = fmaxf(ht[a], 0.0f);
            #pragma unroll
            for (int d = 0; d < 20; d++) px[d] += r * Wt2[(hb + a) * 20 + d];
        }

        // pairwise combine + finalize
        float av[20];
        float nrm = 0.0f;
        #pragma unroll
        for (int d = 0; d < 20; d++) {
            float sp = po[d] + __shfl_xor_sync(0xffffffffu, po[d], 1);
            float tp = px[d] + __shfl_xor_sync(0xffffffffu, px[d], 1);
            av[d] = 0.5f * ((sp + bs2[d]) + (tp + bt2s[d]));
            nrm += av[d] * av[d];
        }
        float* dst = g_a + (size_t)n * VGS;
        #pragma unroll
        for (int d = 0; d < 10; d++) dst[hb / 2 + d] = av[hb / 2 + d];
        if (h == 0) dst[20] = nrm;

    } else {
        // ---- bucket tokens by centroid + build compact worklist ----
        __shared__ int scnt[NC];
        if (tid < NC) scnt[tid] = 0;
        __syncthreads();
        for (int i = tid; i < NTOK; i += 256) {
            int c = Iarr[x[i]];
            int p = atomicAdd(&scnt[c], 1);
            g_tok[c * NTOK + p] = i;
        }
        __syncthreads();
        if (tid < NC) g_cnt[tid] = scnt[tid];
        if (tid == 0) {
            int w = 0;
            for (int c = 0; c < NC; c++) {
                int cnt = scnt[c];
                for (int st = 0; st < cnt; st += CHUNK) g_work[w++] = make_int2(c, st);
            }
            g_nwork = w;
        }
    }
}

// ============ K3: worklist-driven, 32 tokens/block, broadcast candidate rows ============
__global__ void __launch_bounds__(256, 2)
k3_score(const int* __restrict__ x, const int* __restrict__ cand,
         const float* __restrict__ Eemb, float* __restrict__ out) {
    int bid = blockIdx.x;
    if (bid >= g_nwork) return;
    int2 wk = g_work[bid];
    int cid = wk.x, start = wk.y;
    int cnt = g_cnt[cid];
    int nIn = min(CHUNK, cnt - start);

    int tid = threadIdx.x, lane = tid & 31, warp = tid >> 5;

    __shared__ unsigned long long part[8][32][TOPK];  // 20KB
    __shared__ float sw_s[32][12];
    __shared__ int   si_s[32][12];
    __shared__ int   tok_s[32];

    if (tid < 32) tok_s[tid] = g_tok[cid * NTOK + start + min(tid, nIn - 1)];
    __syncthreads();

    int token = tok_s[lane];
    const float* ap = g_a + (size_t)token * VGS;
    float4 A0 = *(const float4*)(ap +  0);
    float4 A1 = *(const float4*)(ap +  4);
    float4 A2 = *(const float4*)(ap +  8);
    float4 A3 = *(const float4*)(ap + 12);
    float4 A4 = *(const float4*)(ap + 16);
    float  an = ap[20];

    int cbase = cid * CANDN;
    const float* vg = g_vg + (size_t)cbase * VGS;

    unsigned long long tk[TOPK];
    #pragma unroll
    for (int q = 0; q < TOPK; q++) tk[q] = 0xFFFFFFFFFFFFFFFFull;

    int j0 = warp * 128;
    #pragma unroll 4
    for (int jj = 0; jj < 128; jj++) {
        int j = j0 + jj;
        const float* vp = vg + (size_t)j * VGS;
        float4 f0 = *(const float4*)(vp +  0);
        float4 f1 = *(const float4*)(vp +  4);
        float4 f2 = *(const float4*)(vp +  8);
        float4 f3 = *(const float4*)(vp + 12);
        float4 f4 = *(const float4*)(vp + 16);
        float  vn = vp[20];
        float dot =
            f0.x * A0.x + f0.y * A0.y + f0.z * A0.z + f0.w * A0.w +
            f1.x * A1.x + f1.y * A1.y + f1.z * A1.z + f1.w * A1.w +
            f2.x * A2.x + f2.y * A2.y + f2.z * A2.z + f2.w * A2.w +
            f3.x * A3.x + f3.y * A3.y + f3.z * A3.z + f3.w * A3.w +
            f4.x * A4.x + f4.y * A4.y + f4.z * A4.z + f4.w * A4.w;
        float d2 = fmaxf(an + vn - 2.0f * dot, 1e-12f);
        unsigned long long key =
            ((unsigned long long)__float_as_uint(d2) << 32) | (unsigned)j;
        if (key < tk[TOPK - 1]) {
            unsigned long long cur = key;
            #pragma unroll
            for (int q = 0; q < TOPK; q++) {
                unsigned long long lo = cur < tk[q] ? cur : tk[q];
                unsigned long long hi = cur < tk[q] ? tk[q] : cur;
                tk[q] = lo; cur = hi;
            }
        }
    }
    #pragma unroll
    for (int q = 0; q < TOPK; q++) part[warp][lane][q] = tk[q];
    __syncthreads();

    if (tid < 32 && tid < nIn) {
        int t = tid;
        unsigned long long h[8];
        int p[8];
        #pragma unroll
        for (int w = 0; w < 8; w++) { h[w] = part[w][t][0]; p[w] = 1; }
        float ssum = 1.0f;   // self term exp(1-1)=1
        #pragma unroll
        for (int k = 0; k < TOPK; k++) {
            unsigned long long best = h[0]; int bw = 0;
            #pragma unroll
            for (int w = 1; w < 8; w++) if (h[w] < best) { best = h[w]; bw = w; }
            #pragma unroll
            for (int w = 0; w < 8; w++)
                if (bw == w) { h[w] = (p[w] < TOPK) ? part[w][t][p[w]] : 0xFFFFFFFFFFFFFFFFull; p[w]++; }
            float d2 = __uint_as_float((unsigned)(best >> 32));
            int   j  = (int)(best & 0xffffffffu);
            float sc = expf(-RHO_C * sqrtf(d2));
            float e  = expf(sc - 1.0f);
            ssum += e;
            sw_s[t][k] = e;
            si_s[t][k] = cand[cbase + j];
        }
        sw_s[t][TOPK] = 1.0f;
        si_s[t][TOPK] = x[tok_s[t]];
        float inv = 1.0f / ssum;
        #pragma unroll
        for (int k = 0; k < 11; k++) sw_s[t][k] *= inv;
    }
    __syncthreads();

    int t  = tid >> 3;
    int pg = tid & 7;
    if (t < nIn) {
        int token2 = tok_s[t];
        float4 a0 = make_float4(0.f, 0.f, 0.f, 0.f), a1 = a0, a2 = a0, a3 = a0;
        #pragma unroll
        for (int k = 0; k < 11; k++) {
            float w = sw_s[t][k];
            const float4* ep = (const float4*)(Eemb + (size_t)si_s[t][k] * HD + pg * 16);
            float4 e0 = ep[0], e1 = ep[1], e2 = ep[2], e3 = ep[3];
            a0.x += w * e0.x; a0.y += w * e0.y; a0.z += w * e0.z; a0.w += w * e0.w;
            a1.x += w * e1.x; a1.y += w * e1.y; a1.z += w * e1.z; a1.w += w * e1.w;
            a2.x += w * e2.x; a2.y += w * e2.y; a2.z += w * e2.z; a2.w += w * e2.w;
            a3.x += w * e3.x; a3.y += w * e3.y; a3.z += w * e3.z; a3.w += w * e3.w;
        }
        float4* op = (float4*)(out + (size_t)token2 * HD + pg * 16);
        op[0] = a0; op[1] = a1; op[2] = a2; op[3] = a3;
    }
}

// ============ launch ============
extern "C" void kernel_launch(void* const* d_in, const int* in_sizes, int n_in,
                              void* d_out, int out_size) {
    const int*   x     = (const int*)  d_in[0];
    const int*   tslot = (const int*)  d_in[1];
    const float* vecs  = (const float*)d_in[2];
    const float* Eemb  = (const float*)d_in[3];
    const int*   Iarr  = (const int*)  d_in[4];
    const int*   cand  = (const int*)  d_in[5];
    const float* te    = (const float*)d_in[6];
    const float* Wseq1 = (const float*)d_in[7];
    const float* bseq1 = (const float*)d_in[8];
    const float* Wseq2 = (const float*)d_in[9];
    const float* bseq2 = (const float*)d_in[10];
    const float* Wto1  = (const float*)d_in[11];
    const float* bto1  = (const float*)d_in[12];
    const float* Wto2  = (const float*)d_in[13];
    const float* bto2  = (const float*)d_in[14];
    const float* Wti1  = (const float*)d_in[15];
    const float* bti1  = (const float*)d_in[16];
    const float* Wti2  = (const float*)d_in[17];
    const float* bti2  = (const float*)d_in[18];
    float* out = (float*)d_out;

    k_mid<<<297, 256>>>(x, tslot, vecs, cand, Iarr, te,
                        Wseq1, bseq1, Wseq2, bseq2,
                        Wto1, bto1, Wto2, bto2,
                        Wti1, bti1, Wti2, bti2);
    k3_score<<<NWORK_MAX, 256>>>(x, cand, Eemb, out);
}